// round 1
// baseline (speedup 1.0000x reference)
#include <cuda_runtime.h>
#include <math.h>

// ---------------------------------------------------------------------------
// Mamba2-style gated linear recurrence block.
//   B=4, S=4096, H=1024
//   Phase 1: fused 5-way projection GEMM (X @ [W_in;W_a;W_b;W_c;W_d]^T) + act
//   Phase 2: chunked parallel linear scan over S
//   Phase 3: output GEMM (Y @ W_out^T) -> d_out, plus final_state
// ---------------------------------------------------------------------------

#define Bdim 4
#define Sdim 4096
#define Hdim 1024
#define Mrows (Bdim * Sdim)        // 16384
#define BSH   (Mrows * Hdim)       // 16,777,216
#define CHUNKS 64
#define CLEN   64                  // CHUNKS * CLEN == Sdim

// -------------------- scratch (static __device__, no allocs) ---------------
__device__ float g_cont[BSH];
__device__ float g_ret[BSH];
__device__ float g_wg[BSH];
__device__ float g_rg[BSH];
__device__ float g_sk[BSH];
__device__ float g_y[BSH];
__device__ float g_Ac[Bdim * CHUNKS * Hdim];
__device__ float g_Bc[Bdim * CHUNKS * Hdim];
__device__ float g_Ss[Bdim * CHUNKS * Hdim];
__device__ float g_maskf[Mrows];
__device__ int   g_mask_mode;      // 0 = u8, 1 = i32, 2 = f32
__device__ float g_fs_dummy[Bdim * Hdim];

// -------------------- mask dtype detection + expansion ---------------------
// The bool attention_mask may be stored as u8, i32, or f32 depending on how
// the harness serializes bools. Detect from the byte pattern of the FIRST
// n bytes only (safe under every interpretation), then expand to float 0/1.
__global__ void detect_mask_kernel(const unsigned char* __restrict__ mb, int n) {
    __shared__ int cflag[4];
    int t = threadIdx.x;
    if (t < 4) cflag[t] = 0;
    __syncthreads();
    for (int i = t; i < n; i += blockDim.x) {
        if (mb[i]) atomicOr(&cflag[i & 3], 1);
    }
    __syncthreads();
    if (t == 0) {
        int c0 = cflag[0], c1 = cflag[1], c2 = cflag[2], c3 = cflag[3];
        int mode = 0;  // default: u8 (safe: reads only n bytes)
        if (c0 | c1 | c2 | c3) {
            if (c0 && !c1 && !c2 && !c3) mode = 1;            // int32 bools
            else if (!c0 && !c1 && (c2 | c3)) mode = 2;       // float 1.0f
        }
        g_mask_mode = mode;
    }
}

__global__ void expand_mask_kernel(const void* __restrict__ mraw, int n) {
    int i = blockIdx.x * blockDim.x + threadIdx.x;
    if (i >= n) return;
    int mode = g_mask_mode;
    bool m;
    if (mode == 1)      m = ((const int*)mraw)[i] != 0;
    else if (mode == 2) m = ((const float*)mraw)[i] != 0.0f;
    else                m = ((const unsigned char*)mraw)[i] != 0;
    g_maskf[i] = m ? 1.0f : 0.0f;
}

// -------------------- packed fp32x2 helpers (sm_100+) ----------------------
__device__ __forceinline__ unsigned long long pack2s(float x) {
    unsigned long long r;
    unsigned a = __float_as_uint(x);
    asm("mov.b64 %0, {%1, %1};" : "=l"(r) : "r"(a));
    return r;
}
__device__ __forceinline__ void unpack2(unsigned long long p, float& x, float& y) {
    unsigned a, b;
    asm("mov.b64 {%0, %1}, %2;" : "=r"(a), "=r"(b) : "l"(p));
    x = __uint_as_float(a);
    y = __uint_as_float(b);
}
__device__ __forceinline__ void ffma2(unsigned long long& d,
                                      unsigned long long a,
                                      unsigned long long b) {
    asm("fma.rn.f32x2 %0, %1, %2, %3;" : "=l"(d) : "l"(a), "l"(b), "l"(d));
}

// -------------------- tiled fp32 GEMM (f32x2 FMA pipe) ---------------------
// C[m][n] = sum_k A[m][k] * W_p[n%1024][k],  p = n / 1024
// BM=BN=128, BK=16, 256 threads, 8x8 per thread (acc packed as f32x2 pairs).
struct GemmArgs {
    const float* W[5];
    float*       outp[5];
    const float* bias[5];
    int          act[5];   // 0 = none, 1 = tanh, 2 = sigmoid(+bias)
};

#define BMt 128
#define BNt 128
#define BKt 16
#define SPAD 4   // smem row padding (stride 132 -> conflict-reducing)

__global__ __launch_bounds__(256, 2)
void gemm_kernel(const float* __restrict__ A, GemmArgs ga) {
    __shared__ float As[BKt][BMt + SPAD];
    __shared__ float Bs[BKt][BNt + SPAD];

    int tid = threadIdx.x;
    int tx = tid & 15;        // 0..15 -> n micro-tile
    int ty = tid >> 4;        // 0..15 -> m micro-tile
    int nBase = blockIdx.x * BNt;
    int mBase = blockIdx.y * BMt;
    int p  = nBase >> 10;               // which projection (tile never straddles)
    const float* __restrict__ W = ga.W[p];
    int o0 = nBase - (p << 10);

    unsigned long long acc[8][4];
#pragma unroll
    for (int i = 0; i < 8; i++)
#pragma unroll
        for (int j = 0; j < 4; j++) acc[i][j] = 0ull;

    for (int k0 = 0; k0 < Hdim; k0 += BKt) {
        // cooperative load: 128 rows x 16 k for both A and W, transposed store
#pragma unroll
        for (int li = 0; li < 2; li++) {
            int l = tid + li * 256;           // 0..511
            int row = l >> 2;                 // 0..127
            int kq  = l & 3;                  // 0..3 (float4 quad)
            float4 v = *(const float4*)(A + (size_t)(mBase + row) * Hdim + k0 + kq * 4);
            As[kq * 4 + 0][row] = v.x;
            As[kq * 4 + 1][row] = v.y;
            As[kq * 4 + 2][row] = v.z;
            As[kq * 4 + 3][row] = v.w;
            float4 w = *(const float4*)(W + (size_t)(o0 + row) * Hdim + k0 + kq * 4);
            Bs[kq * 4 + 0][row] = w.x;
            Bs[kq * 4 + 1][row] = w.y;
            Bs[kq * 4 + 2][row] = w.z;
            Bs[kq * 4 + 3][row] = w.w;
        }
        __syncthreads();

#pragma unroll
        for (int k = 0; k < BKt; k++) {
            float4 a0 = *(const float4*)&As[k][ty * 8];
            float4 a1 = *(const float4*)&As[k][ty * 8 + 4];
            unsigned long long b2[4];
#pragma unroll
            for (int j = 0; j < 4; j++)
                b2[j] = *(const unsigned long long*)&Bs[k][tx * 8 + j * 2];
            float av[8] = {a0.x, a0.y, a0.z, a0.w, a1.x, a1.y, a1.z, a1.w};
#pragma unroll
            for (int i = 0; i < 8; i++) {
                unsigned long long a2 = pack2s(av[i]);
#pragma unroll
                for (int j = 0; j < 4; j++) ffma2(acc[i][j], a2, b2[j]);
            }
        }
        __syncthreads();
    }

    // epilogue: activation + store
    float* __restrict__ outp = ga.outp[p];
    const float* __restrict__ bias = ga.bias[p];
    int act = ga.act[p];
    int ocol = o0 + tx * 8;
#pragma unroll
    for (int i = 0; i < 8; i++) {
        int m = mBase + ty * 8 + i;
        float c[8];
#pragma unroll
        for (int j = 0; j < 4; j++) unpack2(acc[i][j], c[2 * j], c[2 * j + 1]);
        if (act == 2) {
#pragma unroll
            for (int j = 0; j < 8; j++)
                c[j] = 1.0f / (1.0f + expf(-(c[j] + bias[ocol + j])));
        } else if (act == 1) {
#pragma unroll
            for (int j = 0; j < 8; j++) c[j] = tanhf(c[j]);
        }
        float4* dst = (float4*)(outp + (size_t)m * Hdim + ocol);
        dst[0] = make_float4(c[0], c[1], c[2], c[3]);
        dst[1] = make_float4(c[4], c[5], c[6], c[7]);
    }
}

// -------------------- chunked parallel linear scan -------------------------
// Recurrence per channel c=(b,h):  st = aa*st + bb,
//   aa = m ? a : 1,  bb = m ? (1-a)*wg*cont : 0
//   y  = m ? rg*st + sk : 0
// Stage 1: per-chunk (A, B) summaries.  Stage 2: scan over chunk summaries.
// Stage 3: replay within chunk from chunk-start state, emit y.

__global__ void scan_stage1() {
    int id = blockIdx.x * blockDim.x + threadIdx.x;  // B*CHUNKS*H threads
    int h = id & (Hdim - 1);
    int j = (id >> 10) & (CHUNKS - 1);
    int b = id >> 16;                                 // id / (CHUNKS*Hdim)
    float A = 1.0f, Bc = 0.0f;
    size_t base = (size_t)b * Sdim * Hdim + h;
    int s0 = j * CLEN;
#pragma unroll 4
    for (int t = 0; t < CLEN; t++) {
        int s = s0 + t;
        size_t idx = base + (size_t)s * Hdim;
        float a  = g_ret[idx];
        float m  = g_maskf[b * Sdim + s];
        float bx = (1.0f - a) * g_wg[idx] * g_cont[idx];
        float aa = 1.0f + m * (a - 1.0f);
        float bb = m * bx;
        A *= aa;
        Bc = fmaf(aa, Bc, bb);
    }
    int cidx = (b * CHUNKS + j) * Hdim + h;
    g_Ac[cidx] = A;
    g_Bc[cidx] = Bc;
}

__global__ void scan_stage2(const float* __restrict__ state,
                            float* __restrict__ fs_out) {
    int id = blockIdx.x * blockDim.x + threadIdx.x;  // B*H threads
    int h = id & (Hdim - 1);
    int b = id >> 10;
    float st = state[id];
#pragma unroll
    for (int j = 0; j < CHUNKS; j++) {
        int cidx = (b * CHUNKS + j) * Hdim + h;
        g_Ss[cidx] = st;
        st = fmaf(g_Ac[cidx], st, g_Bc[cidx]);
    }
    fs_out[id] = st;
}

__global__ void scan_stage3() {
    int id = blockIdx.x * blockDim.x + threadIdx.x;
    int h = id & (Hdim - 1);
    int j = (id >> 10) & (CHUNKS - 1);
    int b = id >> 16;
    float st = g_Ss[(b * CHUNKS + j) * Hdim + h];
    size_t base = (size_t)b * Sdim * Hdim + h;
    int s0 = j * CLEN;
#pragma unroll 4
    for (int t = 0; t < CLEN; t++) {
        int s = s0 + t;
        size_t idx = base + (size_t)s * Hdim;
        float a  = g_ret[idx];
        float m  = g_maskf[b * Sdim + s];
        float bx = (1.0f - a) * g_wg[idx] * g_cont[idx];
        float aa = 1.0f + m * (a - 1.0f);
        float bb = m * bx;
        st = fmaf(aa, st, bb);
        float yv = m * fmaf(g_rg[idx], st, g_sk[idx]);
        g_y[idx] = yv;
    }
}

// -------------------- launch -----------------------------------------------
extern "C" void kernel_launch(void* const* d_in, const int* in_sizes, int n_in,
                              void* d_out, int out_size) {
    const float* x     = (const float*)d_in[0];
    const float* state = (const float*)d_in[1];
    const void*  mask  = d_in[2];
    const float* W_in  = (const float*)d_in[3];
    const float* W_a   = (const float*)d_in[4];
    const float* b_a   = (const float*)d_in[5];
    const float* W_b   = (const float*)d_in[6];
    const float* b_b   = (const float*)d_in[7];
    const float* W_c   = (const float*)d_in[8];
    const float* b_c   = (const float*)d_in[9];
    const float* W_d   = (const float*)d_in[10];
    const float* W_out = (const float*)d_in[11];
    float* out = (float*)d_out;

    float *p_cont, *p_ret, *p_wg, *p_rg, *p_sk, *p_y, *p_fsdummy;
    cudaGetSymbolAddress((void**)&p_cont, g_cont);
    cudaGetSymbolAddress((void**)&p_ret,  g_ret);
    cudaGetSymbolAddress((void**)&p_wg,   g_wg);
    cudaGetSymbolAddress((void**)&p_rg,   g_rg);
    cudaGetSymbolAddress((void**)&p_sk,   g_sk);
    cudaGetSymbolAddress((void**)&p_y,    g_y);
    cudaGetSymbolAddress((void**)&p_fsdummy, g_fs_dummy);

    // Mask canonicalization
    detect_mask_kernel<<<1, 256>>>((const unsigned char*)mask, Mrows);
    expand_mask_kernel<<<Mrows / 256, 256>>>(mask, Mrows);

    // Phase 1: fused 5-projection GEMM
    GemmArgs g1;
    g1.W[0] = W_in; g1.W[1] = W_a; g1.W[2] = W_b; g1.W[3] = W_c; g1.W[4] = W_d;
    g1.outp[0] = p_cont; g1.outp[1] = p_ret; g1.outp[2] = p_wg;
    g1.outp[3] = p_rg;   g1.outp[4] = p_sk;
    g1.bias[0] = nullptr; g1.bias[1] = b_a; g1.bias[2] = b_b;
    g1.bias[3] = b_c;     g1.bias[4] = nullptr;
    g1.act[0] = 1; g1.act[1] = 2; g1.act[2] = 2; g1.act[3] = 2; g1.act[4] = 0;
    dim3 grid1(5 * Hdim / BNt, Mrows / BMt);   // (40, 128)
    gemm_kernel<<<grid1, 256>>>(x, g1);

    // Phase 2: chunked scan
    float* fsPtr = (out_size >= BSH + Bdim * Hdim) ? (out + BSH) : p_fsdummy;
    scan_stage1<<<(Bdim * CHUNKS * Hdim) / 256, 256>>>();
    scan_stage2<<<(Bdim * Hdim) / 256, 256>>>(state, fsPtr);
    scan_stage3<<<(Bdim * CHUNKS * Hdim) / 256, 256>>>();

    // Phase 3: output GEMM -> d_out
    GemmArgs g2;
    for (int i = 0; i < 5; i++) {
        g2.W[i] = W_out; g2.outp[i] = out; g2.bias[i] = nullptr; g2.act[i] = 0;
    }
    dim3 grid2(Hdim / BNt, Mrows / BMt);       // (8, 128)
    gemm_kernel<<<grid2, 256>>>(p_y, g2);
}

// round 3
// speedup vs baseline: 2.5927x; 2.5927x over previous
#include <cuda_runtime.h>
#include <cuda_bf16.h>
#include <math.h>
#include <stdint.h>

// ---------------------------------------------------------------------------
// Mamba2 block: bf16x3 split-precision mma.sync GEMMs + chunked scan
//   (tcgen05 unavailable at compute_103 virtual target -> HMMA path)
// ---------------------------------------------------------------------------

#define Bdim 4
#define Sdim 4096
#define Hdim 1024
#define Mrows (Bdim * Sdim)        // 16384
#define BSH   (Mrows * Hdim)
#define CHUNKS 64
#define CLEN   64

// -------------------- scratch (static __device__, no allocs) ---------------
__device__ __nv_bfloat16 g_xh[BSH];
__device__ __nv_bfloat16 g_xl[BSH];
__device__ __nv_bfloat16 g_yh[BSH];
__device__ __nv_bfloat16 g_yl[BSH];
__device__ __nv_bfloat16 g_w5h[5 * Hdim * Hdim];
__device__ __nv_bfloat16 g_w5l[5 * Hdim * Hdim];
__device__ __nv_bfloat16 g_woh[Hdim * Hdim];
__device__ __nv_bfloat16 g_wol[Hdim * Hdim];
__device__ float g_cont[BSH];
__device__ float g_ret[BSH];
__device__ float g_wg[BSH];
__device__ float g_rg[BSH];
__device__ float g_sk[BSH];
__device__ float g_Ac[Bdim * CHUNKS * Hdim];
__device__ float g_Bc[Bdim * CHUNKS * Hdim];
__device__ float g_Ss[Bdim * CHUNKS * Hdim];
__device__ float g_maskf[Mrows];
__device__ int   g_mask_mode;
__device__ float g_fs_dummy[Bdim * Hdim];

// -------------------- mask dtype detection + expansion ---------------------
__global__ void detect_mask_kernel(const unsigned char* __restrict__ mb, int n) {
    __shared__ int cflag[4];
    int t = threadIdx.x;
    if (t < 4) cflag[t] = 0;
    __syncthreads();
    for (int i = t; i < n; i += blockDim.x)
        if (mb[i]) atomicOr(&cflag[i & 3], 1);
    __syncthreads();
    if (t == 0) {
        int c0 = cflag[0], c1 = cflag[1], c2 = cflag[2], c3 = cflag[3];
        int mode = 0;
        if (c0 | c1 | c2 | c3) {
            if (c0 && !c1 && !c2 && !c3) mode = 1;
            else if (!c0 && !c1 && (c2 | c3)) mode = 2;
        }
        g_mask_mode = mode;
    }
}

__global__ void expand_mask_kernel(const void* __restrict__ mraw, int n) {
    int i = blockIdx.x * blockDim.x + threadIdx.x;
    if (i >= n) return;
    int mode = g_mask_mode;
    bool m;
    if (mode == 1)      m = ((const int*)mraw)[i] != 0;
    else if (mode == 2) m = ((const float*)mraw)[i] != 0.0f;
    else                m = ((const unsigned char*)mraw)[i] != 0;
    g_maskf[i] = m ? 1.0f : 0.0f;
}

// -------------------- fp32 -> bf16 hi/lo split ------------------------------
__global__ void split_kernel(const float* __restrict__ in,
                             __nv_bfloat16* __restrict__ hi,
                             __nv_bfloat16* __restrict__ lo, int n) {
    int i = (blockIdx.x * blockDim.x + threadIdx.x) * 4;
    if (i >= n) return;
    float4 v = *(const float4*)(in + i);
    __nv_bfloat16 h0 = __float2bfloat16(v.x);
    __nv_bfloat16 h1 = __float2bfloat16(v.y);
    __nv_bfloat16 h2 = __float2bfloat16(v.z);
    __nv_bfloat16 h3 = __float2bfloat16(v.w);
    __nv_bfloat16 l0 = __float2bfloat16(v.x - __bfloat162float(h0));
    __nv_bfloat16 l1 = __float2bfloat16(v.y - __bfloat162float(h1));
    __nv_bfloat16 l2 = __float2bfloat16(v.z - __bfloat162float(h2));
    __nv_bfloat16 l3 = __float2bfloat16(v.w - __bfloat162float(h3));
    ((__nv_bfloat162*)(hi + i))[0] = __halves2bfloat162(h0, h1);
    ((__nv_bfloat162*)(hi + i))[1] = __halves2bfloat162(h2, h3);
    ((__nv_bfloat162*)(lo + i))[0] = __halves2bfloat162(l0, l1);
    ((__nv_bfloat162*)(lo + i))[1] = __halves2bfloat162(l2, l3);
}

// -------------------- PTX helpers ------------------------------------------
__device__ __forceinline__ uint32_t su32(const void* p) {
    uint32_t a;
    asm("{ .reg .u64 t; cvta.to.shared.u64 t, %1; cvt.u32.u64 %0, t; }"
        : "=r"(a) : "l"(p));
    return a;
}
__device__ __forceinline__ void cpa16(uint32_t s, const void* g) {
    asm volatile("cp.async.cg.shared.global [%0], [%1], 16;" :: "r"(s), "l"(g));
}
__device__ __forceinline__ void cpa_commit() {
    asm volatile("cp.async.commit_group;" ::: "memory");
}
__device__ __forceinline__ void cpa_wait1() {
    asm volatile("cp.async.wait_group 1;" ::: "memory");
}
__device__ __forceinline__ void cpa_wait0() {
    asm volatile("cp.async.wait_group 0;" ::: "memory");
}
__device__ __forceinline__ void ldm_x4(uint32_t* r, uint32_t addr) {
    asm volatile("ldmatrix.sync.aligned.m8n8.x4.shared.b16 {%0,%1,%2,%3}, [%4];"
                 : "=r"(r[0]), "=r"(r[1]), "=r"(r[2]), "=r"(r[3]) : "r"(addr));
}
__device__ __forceinline__ void mma_bf16(float* d, const uint32_t* a,
                                         const uint32_t* b) {
    asm volatile(
        "mma.sync.aligned.m16n8k16.row.col.f32.bf16.bf16.f32 "
        "{%0,%1,%2,%3}, {%4,%5,%6,%7}, {%8,%9}, {%0,%1,%2,%3};"
        : "+f"(d[0]), "+f"(d[1]), "+f"(d[2]), "+f"(d[3])
        : "r"(a[0]), "r"(a[1]), "r"(a[2]), "r"(a[3]), "r"(b[0]), "r"(b[1]));
}

// -------------------- mma.sync GEMM ----------------------------------------
// C[m][n] = sum_k (Ah+Al)[m][k] * (Wh+Wl)[n][k]  (3 split products)
// BM=BN=128, BK=64 (bf16, 128B rows, SW128 swizzle), 256 threads, 2 stages.

#define TILE_BYTES (128 * 64 * 2)      // 16 KB
#define STAGE_BYTES (4 * TILE_BYTES)   // 64 KB (Ah, Al, Bh, Bl)
#define SMEM_TOTAL (2 * STAGE_BYTES)   // 128 KB
#define NSTAGES (Hdim / 64)            // 16

struct GArgs {
    const __nv_bfloat16 *Ah, *Al, *Wh, *Wl;
    float*       outp[5];
    const float* bias[5];
    int          act[5];      // 0 none, 1 tanh, 2 sigmoid(+bias)
};

__device__ __forceinline__ uint32_t swadr(uint32_t base, int row, int chunk) {
    return base + row * 128 + ((chunk ^ (row & 7)) << 4);
}

__global__ __launch_bounds__(256, 1)
void gemm_mma_kernel(GArgs ga) {
    extern __shared__ char smem[];
    uint32_t sb = su32(smem);
    int tid = threadIdx.x;
    int wid = tid >> 5, lane = tid & 31;
    int wm = wid >> 2, wn = wid & 3;           // 2 x 4 warp grid
    int m0 = wm * 64, n0 = wn * 32;            // warp tile 64x32

    int mBase = blockIdx.y * 128;
    int nBase = blockIdx.x * 128;
    const __nv_bfloat16* srcs[4] = {
        ga.Ah + (size_t)mBase * Hdim,
        ga.Al + (size_t)mBase * Hdim,
        ga.Wh + (size_t)nBase * Hdim,
        ga.Wl + (size_t)nBase * Hdim
    };

    float acc[4][4][4];
#pragma unroll
    for (int i = 0; i < 4; i++)
#pragma unroll
        for (int j = 0; j < 4; j++)
#pragma unroll
            for (int e = 0; e < 4; e++) acc[i][j][e] = 0.0f;

    // per-thread load slots: 16 chunks of 16B per stage
    auto load_stage = [&](int s) {
        uint32_t so = sb + (s & 1) * STAGE_BYTES;
        int k0 = s * 64;
#pragma unroll
        for (int i = 0; i < 16; i++) {
            int c = tid + i * 256;             // 0..4095
            int T = c >> 10;                   // tile 0..3
            int ct = c & 1023;
            int row = ct >> 3;
            int col = ct & 7;
            cpa16(swadr(so + T * TILE_BYTES, row, col),
                  srcs[T] + (size_t)row * Hdim + k0 + col * 8);
        }
    };

    load_stage(0);
    cpa_commit();

    // ldmatrix lane addressing (within a 128x64 tile, 128B rows)
    int aRow = (lane & 15);                    // + m row base
    int aKC  = (lane >> 4);                    // k-chunk offset 0/1
    int bRow = (lane & 7) + ((lane >> 4) << 3);  // n row: lanes16-31 -> +8
    int bKC  = (lane >> 3) & 1;                // k-chunk offset 0/1

    for (int s = 0; s < NSTAGES; s++) {
        if (s + 1 < NSTAGES) {
            load_stage(s + 1);
            cpa_commit();
            cpa_wait1();
        } else {
            cpa_wait0();
        }
        __syncthreads();

        uint32_t so = sb + (s & 1) * STAGE_BYTES;
        uint32_t tAh = so;
        uint32_t tAl = so + TILE_BYTES;
        uint32_t tBh = so + 2 * TILE_BYTES;
        uint32_t tBl = so + 3 * TILE_BYTES;

#pragma unroll
        for (int kk = 0; kk < 4; kk++) {       // four k16 steps in the stage
            int kc = kk * 2;
            // B fragments: 2 x4 loads each for hi and lo (covers n0..n0+31)
            uint32_t bh[8], bl[8];
#pragma unroll
            for (int half = 0; half < 2; half++) {
                int nrow = n0 + half * 16 + bRow;
                ldm_x4(bh + half * 4, swadr(tBh, nrow, kc + bKC));
                ldm_x4(bl + half * 4, swadr(tBl, nrow, kc + bKC));
            }
#pragma unroll
            for (int mf = 0; mf < 4; mf++) {
                uint32_t ah[4], al[4];
                int mrow = m0 + mf * 16 + aRow;
                ldm_x4(ah, swadr(tAh, mrow, kc + aKC));
                ldm_x4(al, swadr(tAl, mrow, kc + aKC));
#pragma unroll
                for (int nf = 0; nf < 4; nf++) {
                    uint32_t* bhf = bh + (nf >> 1) * 4 + (nf & 1) * 2;
                    uint32_t* blf = bl + (nf >> 1) * 4 + (nf & 1) * 2;
                    mma_bf16(acc[mf][nf], ah, bhf);
                    mma_bf16(acc[mf][nf], ah, blf);
                    mma_bf16(acc[mf][nf], al, bhf);
                }
            }
        }
        __syncthreads();
    }

    // ---------------- epilogue: activation + fp32 store ----------------
    int p = nBase >> 10;
    float* __restrict__ outp = ga.outp[p];
    const float* __restrict__ bias = ga.bias[p];
    int act = ga.act[p];
    int ocol0 = (nBase & 1023) + n0;

#pragma unroll
    for (int mf = 0; mf < 4; mf++) {
#pragma unroll
        for (int rh = 0; rh < 2; rh++) {
            int m = mBase + m0 + mf * 16 + (lane >> 2) + rh * 8;
#pragma unroll
            for (int nf = 0; nf < 4; nf++) {
                int col = ocol0 + nf * 8 + (lane & 3) * 2;
                float v0 = acc[mf][nf][rh * 2 + 0];
                float v1 = acc[mf][nf][rh * 2 + 1];
                if (act == 1) {
                    v0 = tanhf(v0);
                    v1 = tanhf(v1);
                } else if (act == 2) {
                    v0 = 1.0f / (1.0f + expf(-(v0 + bias[col])));
                    v1 = 1.0f / (1.0f + expf(-(v1 + bias[col + 1])));
                }
                *(float2*)(outp + (size_t)m * Hdim + col) = make_float2(v0, v1);
            }
        }
    }
}

// -------------------- chunked parallel linear scan -------------------------
__global__ void scan_stage1() {
    int id = blockIdx.x * blockDim.x + threadIdx.x;
    int h = id & (Hdim - 1);
    int j = (id >> 10) & (CHUNKS - 1);
    int b = id >> 16;
    float A = 1.0f, Bc = 0.0f;
    size_t base = (size_t)b * Sdim * Hdim + h;
    int s0 = j * CLEN;
#pragma unroll 4
    for (int t = 0; t < CLEN; t++) {
        int s = s0 + t;
        size_t idx = base + (size_t)s * Hdim;
        float a  = g_ret[idx];
        float m  = g_maskf[b * Sdim + s];
        float bx = (1.0f - a) * g_wg[idx] * g_cont[idx];
        float aa = 1.0f + m * (a - 1.0f);
        float bb = m * bx;
        A *= aa;
        Bc = fmaf(aa, Bc, bb);
    }
    int cidx = (b * CHUNKS + j) * Hdim + h;
    g_Ac[cidx] = A;
    g_Bc[cidx] = Bc;
}

__global__ void scan_stage2(const float* __restrict__ state,
                            float* __restrict__ fs_out) {
    int id = blockIdx.x * blockDim.x + threadIdx.x;
    int h = id & (Hdim - 1);
    int b = id >> 10;
    float st = state[id];
#pragma unroll
    for (int j = 0; j < CHUNKS; j++) {
        int cidx = (b * CHUNKS + j) * Hdim + h;
        g_Ss[cidx] = st;
        st = fmaf(g_Ac[cidx], st, g_Bc[cidx]);
    }
    fs_out[id] = st;
}

__global__ void scan_stage3() {
    int id = blockIdx.x * blockDim.x + threadIdx.x;
    int h = id & (Hdim - 1);
    int j = (id >> 10) & (CHUNKS - 1);
    int b = id >> 16;
    float st = g_Ss[(b * CHUNKS + j) * Hdim + h];
    size_t base = (size_t)b * Sdim * Hdim + h;
    int s0 = j * CLEN;
#pragma unroll 4
    for (int t = 0; t < CLEN; t++) {
        int s = s0 + t;
        size_t idx = base + (size_t)s * Hdim;
        float a  = g_ret[idx];
        float m  = g_maskf[b * Sdim + s];
        float bx = (1.0f - a) * g_wg[idx] * g_cont[idx];
        float aa = 1.0f + m * (a - 1.0f);
        float bb = m * bx;
        st = fmaf(aa, st, bb);
        float yv = m * fmaf(g_rg[idx], st, g_sk[idx]);
        __nv_bfloat16 hh = __float2bfloat16(yv);
        g_yh[idx] = hh;
        g_yl[idx] = __float2bfloat16(yv - __bfloat162float(hh));
    }
}

// -------------------- launch -----------------------------------------------
extern "C" void kernel_launch(void* const* d_in, const int* in_sizes, int n_in,
                              void* d_out, int out_size) {
    const float* x     = (const float*)d_in[0];
    const float* state = (const float*)d_in[1];
    const void*  mask  = d_in[2];
    const float* W_in  = (const float*)d_in[3];
    const float* W_a   = (const float*)d_in[4];
    const float* b_a   = (const float*)d_in[5];
    const float* W_b   = (const float*)d_in[6];
    const float* b_b   = (const float*)d_in[7];
    const float* W_c   = (const float*)d_in[8];
    const float* b_c   = (const float*)d_in[9];
    const float* W_d   = (const float*)d_in[10];
    const float* W_out = (const float*)d_in[11];
    float* out = (float*)d_out;

    __nv_bfloat16 *p_xh, *p_xl, *p_yh, *p_yl, *p_w5h, *p_w5l, *p_woh, *p_wol;
    float *p_cont, *p_ret, *p_wg, *p_rg, *p_sk, *p_fsdummy;
    cudaGetSymbolAddress((void**)&p_xh,  g_xh);
    cudaGetSymbolAddress((void**)&p_xl,  g_xl);
    cudaGetSymbolAddress((void**)&p_yh,  g_yh);
    cudaGetSymbolAddress((void**)&p_yl,  g_yl);
    cudaGetSymbolAddress((void**)&p_w5h, g_w5h);
    cudaGetSymbolAddress((void**)&p_w5l, g_w5l);
    cudaGetSymbolAddress((void**)&p_woh, g_woh);
    cudaGetSymbolAddress((void**)&p_wol, g_wol);
    cudaGetSymbolAddress((void**)&p_cont, g_cont);
    cudaGetSymbolAddress((void**)&p_ret,  g_ret);
    cudaGetSymbolAddress((void**)&p_wg,   g_wg);
    cudaGetSymbolAddress((void**)&p_rg,   g_rg);
    cudaGetSymbolAddress((void**)&p_sk,   g_sk);
    cudaGetSymbolAddress((void**)&p_fsdummy, g_fs_dummy);

    cudaFuncSetAttribute(gemm_mma_kernel,
                         cudaFuncAttributeMaxDynamicSharedMemorySize, SMEM_TOTAL);

    // mask canonicalization
    detect_mask_kernel<<<1, 256>>>((const unsigned char*)mask, Mrows);
    expand_mask_kernel<<<Mrows / 256, 256>>>(mask, Mrows);

    // splits
    const int WN = Hdim * Hdim;
    split_kernel<<<BSH / 4 / 256, 256>>>(x, p_xh, p_xl, BSH);
    split_kernel<<<WN / 4 / 256, 256>>>(W_in, p_w5h + 0 * (size_t)WN, p_w5l + 0 * (size_t)WN, WN);
    split_kernel<<<WN / 4 / 256, 256>>>(W_a,  p_w5h + 1 * (size_t)WN, p_w5l + 1 * (size_t)WN, WN);
    split_kernel<<<WN / 4 / 256, 256>>>(W_b,  p_w5h + 2 * (size_t)WN, p_w5l + 2 * (size_t)WN, WN);
    split_kernel<<<WN / 4 / 256, 256>>>(W_c,  p_w5h + 3 * (size_t)WN, p_w5l + 3 * (size_t)WN, WN);
    split_kernel<<<WN / 4 / 256, 256>>>(W_d,  p_w5h + 4 * (size_t)WN, p_w5l + 4 * (size_t)WN, WN);
    split_kernel<<<WN / 4 / 256, 256>>>(W_out, p_woh, p_wol, WN);

    // Phase 1: fused 5-projection GEMM
    GArgs g1;
    g1.Ah = p_xh; g1.Al = p_xl; g1.Wh = p_w5h; g1.Wl = p_w5l;
    g1.outp[0] = p_cont; g1.outp[1] = p_ret; g1.outp[2] = p_wg;
    g1.outp[3] = p_rg;   g1.outp[4] = p_sk;
    g1.bias[0] = nullptr; g1.bias[1] = b_a; g1.bias[2] = b_b;
    g1.bias[3] = b_c;     g1.bias[4] = nullptr;
    g1.act[0] = 1; g1.act[1] = 2; g1.act[2] = 2; g1.act[3] = 2; g1.act[4] = 0;
    gemm_mma_kernel<<<dim3(40, 128), 256, SMEM_TOTAL>>>(g1);

    // Phase 2: chunked scan
    float* fsPtr = (out_size >= BSH + Bdim * Hdim) ? (out + BSH) : p_fsdummy;
    scan_stage1<<<(Bdim * CHUNKS * Hdim) / 256, 256>>>();
    scan_stage2<<<(Bdim * Hdim) / 256, 256>>>(state, fsPtr);
    scan_stage3<<<(Bdim * CHUNKS * Hdim) / 256, 256>>>();

    // Phase 3: output GEMM
    GArgs g2;
    g2.Ah = p_yh; g2.Al = p_yl; g2.Wh = p_woh; g2.Wl = p_wol;
    for (int i = 0; i < 5; i++) {
        g2.outp[i] = out; g2.bias[i] = nullptr; g2.act[i] = 0;
    }
    gemm_mma_kernel<<<dim3(8, 128), 256, SMEM_TOTAL>>>(g2);
}